// round 15
// baseline (speedup 1.0000x reference)
#include <cuda_runtime.h>
#include <math.h>

// Problem constants
#define EMB   1024
#define HS    64
#define BB    4
#define TT    4096
#define NROWS (BB * TT)   // 16384

// Scratch for projected q, k, v (fp32) — device globals (no allocations allowed)
__device__ float g_q[NROWS * HS];
__device__ float g_k[NROWS * HS];
__device__ float g_v[NROWS * HS];

// ---------------------------------------------------------------------------
// Fused projection kernel: q = x@Wq, k = x@Wk, v = x@Wv
// Reads each x row once, produces all three projections.
// grid = NROWS/64 = 256 blocks, 256 threads. BM=64, BN=64 (full head), BK=32.
// Thread micro-tile: 4 rows x 4 cols per output matrix (48 accumulators).
// ---------------------------------------------------------------------------
__global__ __launch_bounds__(256) void proj_kernel(
    const float* __restrict__ x,
    const float* __restrict__ Wq,
    const float* __restrict__ Wk,
    const float* __restrict__ Wv)
{
    __shared__ float Xs[64][33];        // padded: conflict-free row reads
    __shared__ float Ws[3][32][64];

    const int tid = threadIdx.x;
    const int tx  = tid & 15;           // output-col group (16)
    const int ty  = tid >> 4;           // output-row group (16)
    const int row0 = blockIdx.x * 64;

    float acc[3][4][4];
#pragma unroll
    for (int m = 0; m < 3; m++)
#pragma unroll
        for (int i = 0; i < 4; i++)
#pragma unroll
            for (int j = 0; j < 4; j++) acc[m][i][j] = 0.0f;

    const float* Wp[3] = {Wq, Wk, Wv};

    for (int k0 = 0; k0 < EMB; k0 += 32) {
        // X tile 64x32 = 512 float4 (2 per thread), coalesced
#pragma unroll
        for (int l = 0; l < 2; l++) {
            int idx = tid + l * 256;            // 0..511
            int r   = idx >> 3;                 // 8 float4 per row
            int c4  = idx & 7;
            float4 v = *(const float4*)(&x[(size_t)(row0 + r) * EMB + k0 + c4 * 4]);
            Xs[r][c4 * 4 + 0] = v.x;
            Xs[r][c4 * 4 + 1] = v.y;
            Xs[r][c4 * 4 + 2] = v.z;
            Xs[r][c4 * 4 + 3] = v.w;
        }
        // W tiles: 3 x (32x64) = 3 x 512 float4
#pragma unroll
        for (int m = 0; m < 3; m++) {
#pragma unroll
            for (int l = 0; l < 2; l++) {
                int idx = tid + l * 256;
                int r   = idx >> 4;             // 16 float4 per row
                int c4  = idx & 15;
                float4 v = *(const float4*)(&Wp[m][(size_t)(k0 + r) * HS + c4 * 4]);
                *(float4*)(&Ws[m][r][c4 * 4]) = v;
            }
        }
        __syncthreads();

#pragma unroll
        for (int kk = 0; kk < 32; kk++) {
            float xv[4];
#pragma unroll
            for (int i = 0; i < 4; i++) xv[i] = Xs[ty * 4 + i][kk];
#pragma unroll
            for (int m = 0; m < 3; m++) {
                float wv[4];
#pragma unroll
                for (int j = 0; j < 4; j++) wv[j] = Ws[m][kk][tx * 4 + j];
#pragma unroll
                for (int i = 0; i < 4; i++)
#pragma unroll
                    for (int j = 0; j < 4; j++)
                        acc[m][i][j] += xv[i] * wv[j];
            }
        }
        __syncthreads();
    }

#pragma unroll
    for (int i = 0; i < 4; i++) {
        size_t r = (size_t)(row0 + ty * 4 + i) * HS + tx * 4;
#pragma unroll
        for (int j = 0; j < 4; j++) g_q[r + j] = acc[0][i][j];
#pragma unroll
        for (int j = 0; j < 4; j++) g_k[r + j] = acc[1][i][j];
#pragma unroll
        for (int j = 0; j < 4; j++) g_v[r + j] = acc[2][i][j];
    }
}

// ---------------------------------------------------------------------------
// Flash-attention kernel (causal), fp32.
// grid = (T/64, B), 256 threads. BM = BN = 64, D = 64.
// Online softmax: running max m[i], running sum l[i] per query row.
// Smem: Qs[64][65], KP[64][65] (K tile, reused for P), Vs[64][65] -> 49920 B.
// ---------------------------------------------------------------------------
__global__ __launch_bounds__(256) void attn_kernel(float* __restrict__ out)
{
    extern __shared__ float sm[];
    float* Qs = sm;                 // 64*65
    float* KP = sm + 64 * 65;       // 64*65 (K, then P)
    float* Vs = sm + 2 * 64 * 65;   // 64*65

    const int tid = threadIdx.x;
    const int tx  = tid & 15;
    const int ty  = tid >> 4;
    const int b   = blockIdx.y;
    const int i0  = blockIdx.x * 64;                 // query tile start
    const size_t base = (size_t)b * TT * HS;

    // Load Q tile, folding in scale = EMB^-0.5 = 1/32 (exact power of two)
    const float sc = 0.03125f;
#pragma unroll
    for (int l = 0; l < 4; l++) {
        int idx = tid + l * 256;                     // 64 rows * 16 float4
        int r   = idx >> 4;
        int c4  = idx & 15;
        float4 v = *(const float4*)(&g_q[base + (size_t)(i0 + r) * HS + c4 * 4]);
        Qs[r * 65 + c4 * 4 + 0] = v.x * sc;
        Qs[r * 65 + c4 * 4 + 1] = v.y * sc;
        Qs[r * 65 + c4 * 4 + 2] = v.z * sc;
        Qs[r * 65 + c4 * 4 + 3] = v.w * sc;
    }

    float m[4], lsum[4], acc[4][4];
#pragma unroll
    for (int i = 0; i < 4; i++) { m[i] = -1e30f; lsum[i] = 0.0f; }
#pragma unroll
    for (int i = 0; i < 4; i++)
#pragma unroll
        for (int j = 0; j < 4; j++) acc[i][j] = 0.0f;

    for (int j0 = 0; j0 <= i0; j0 += 64) {
        __syncthreads();   // previous iteration's PV reads of KP/Vs complete

        // Load K, V tiles (coalesced float4 from global, scalar stores to padded smem)
#pragma unroll
        for (int l = 0; l < 4; l++) {
            int idx = tid + l * 256;
            int r   = idx >> 4;
            int c4  = idx & 15;
            float4 kv = *(const float4*)(&g_k[base + (size_t)(j0 + r) * HS + c4 * 4]);
            KP[r * 65 + c4 * 4 + 0] = kv.x;
            KP[r * 65 + c4 * 4 + 1] = kv.y;
            KP[r * 65 + c4 * 4 + 2] = kv.z;
            KP[r * 65 + c4 * 4 + 3] = kv.w;
            float4 vv = *(const float4*)(&g_v[base + (size_t)(j0 + r) * HS + c4 * 4]);
            Vs[r * 65 + c4 * 4 + 0] = vv.x;
            Vs[r * 65 + c4 * 4 + 1] = vv.y;
            Vs[r * 65 + c4 * 4 + 2] = vv.z;
            Vs[r * 65 + c4 * 4 + 3] = vv.w;
        }
        __syncthreads();

        // S = Q * K^T  (thread owns rows ty*4.., cols tx*4..)
        float s[4][4];
#pragma unroll
        for (int i = 0; i < 4; i++)
#pragma unroll
            for (int j = 0; j < 4; j++) s[i][j] = 0.0f;

#pragma unroll 8
        for (int kk = 0; kk < 64; kk++) {
            float qv[4], kv[4];
#pragma unroll
            for (int i = 0; i < 4; i++) qv[i] = Qs[(ty * 4 + i) * 65 + kk];
#pragma unroll
            for (int j = 0; j < 4; j++) kv[j] = KP[(tx * 4 + j) * 65 + kk];
#pragma unroll
            for (int i = 0; i < 4; i++)
#pragma unroll
                for (int j = 0; j < 4; j++) s[i][j] += qv[i] * kv[j];
        }

        // Causal mask (only the diagonal tile needs it)
        if (j0 == i0) {
#pragma unroll
            for (int i = 0; i < 4; i++) {
                int qidx = ty * 4 + i;
#pragma unroll
                for (int j = 0; j < 4; j++) {
                    if (tx * 4 + j > qidx) s[i][j] = -1e30f;
                }
            }
        }

        // Online softmax per row (row spans 16 consecutive lanes -> shfl width 16)
#pragma unroll
        for (int i = 0; i < 4; i++) {
            float mloc = fmaxf(fmaxf(s[i][0], s[i][1]), fmaxf(s[i][2], s[i][3]));
#pragma unroll
            for (int off = 8; off >= 1; off >>= 1)
                mloc = fmaxf(mloc, __shfl_xor_sync(0xffffffffu, mloc, off, 16));
            float mnew = fmaxf(m[i], mloc);
            float corr = __expf(m[i] - mnew);
            m[i] = mnew;

            float psum = 0.0f;
#pragma unroll
            for (int j = 0; j < 4; j++) {
                float p = __expf(s[i][j] - mnew);   // masked -1e30 underflows to 0
                s[i][j] = p;
                psum += p;
            }
#pragma unroll
            for (int off = 8; off >= 1; off >>= 1)
                psum += __shfl_xor_sync(0xffffffffu, psum, off, 16);

            lsum[i] = lsum[i] * corr + psum;
#pragma unroll
            for (int j = 0; j < 4; j++) acc[i][j] *= corr;
        }

        __syncthreads();   // all warps done reading K from KP

        // Write P into KP (same [row][65] layout)
#pragma unroll
        for (int i = 0; i < 4; i++)
#pragma unroll
            for (int j = 0; j < 4; j++)
                KP[(ty * 4 + i) * 65 + tx * 4 + j] = s[i][j];
        __syncthreads();

        // O += P @ V   (contraction over key index ss)
#pragma unroll 8
        for (int ss = 0; ss < 64; ss++) {
            float pv[4], vv[4];
#pragma unroll
            for (int i = 0; i < 4; i++) pv[i] = KP[(ty * 4 + i) * 65 + ss];
#pragma unroll
            for (int j = 0; j < 4; j++) vv[j] = Vs[ss * 65 + tx * 4 + j];
#pragma unroll
            for (int i = 0; i < 4; i++)
#pragma unroll
                for (int j = 0; j < 4; j++) acc[i][j] += pv[i] * vv[j];
        }
    }

    // Epilogue: out = acc / l
#pragma unroll
    for (int i = 0; i < 4; i++) {
        float inv = 1.0f / lsum[i];
        size_t r = base + (size_t)(i0 + ty * 4 + i) * HS + tx * 4;
#pragma unroll
        for (int j = 0; j < 4; j++) out[r + j] = acc[i][j] * inv;
    }
}

// ---------------------------------------------------------------------------
// kernel_launch: proj -> attention. Graph-capturable, allocation-free.
// Inputs (metadata order): x [B,T,E], Wq [E,H], Wk [E,H], Wv [E,H], all fp32.
// Output: [B,T,H] fp32.
// ---------------------------------------------------------------------------
extern "C" void kernel_launch(void* const* d_in, const int* in_sizes, int n_in,
                              void* d_out, int out_size)
{
    const float* x  = (const float*)d_in[0];
    const float* Wq = (const float*)d_in[1];
    const float* Wk = (const float*)d_in[2];
    const float* Wv = (const float*)d_in[3];
    float* out = (float*)d_out;

    proj_kernel<<<NROWS / 64, 256>>>(x, Wq, Wk, Wv);

    const int smem = 3 * 64 * 65 * (int)sizeof(float);   // 49920 B > 48K default
    cudaFuncSetAttribute(attn_kernel, cudaFuncAttributeMaxDynamicSharedMemorySize, smem);
    attn_kernel<<<dim3(TT / 64, BB), 256, smem>>>(out);
}

// round 16
// speedup vs baseline: 1.0012x; 1.0012x over previous
#include <cuda_runtime.h>
#include <math.h>

// Problem constants
#define EMB   1024
#define HS    64
#define BB    4
#define TT    4096
#define NROWS (BB * TT)   // 16384

// Scratch for projected q, k, v (fp32) — device globals (no allocations allowed)
__device__ float g_q[NROWS * HS];
__device__ float g_k[NROWS * HS];
__device__ float g_v[NROWS * HS];

// ---------------------------------------------------------------------------
// Fused projection kernel: q = x@Wq, k = x@Wk, v = x@Wv
// Reads each x row once, produces all three projections.
// grid = NROWS/64 = 256 blocks, 256 threads. BM=64, BN=64 (full head), BK=32.
// Thread micro-tile: 4 rows x 4 cols per output matrix (48 accumulators).
// ---------------------------------------------------------------------------
__global__ __launch_bounds__(256) void proj_kernel(
    const float* __restrict__ x,
    const float* __restrict__ Wq,
    const float* __restrict__ Wk,
    const float* __restrict__ Wv)
{
    __shared__ float Xs[64][33];        // padded: conflict-free row reads
    __shared__ float Ws[3][32][64];

    const int tid = threadIdx.x;
    const int tx  = tid & 15;           // output-col group (16)
    const int ty  = tid >> 4;           // output-row group (16)
    const int row0 = blockIdx.x * 64;

    float acc[3][4][4];
#pragma unroll
    for (int m = 0; m < 3; m++)
#pragma unroll
        for (int i = 0; i < 4; i++)
#pragma unroll
            for (int j = 0; j < 4; j++) acc[m][i][j] = 0.0f;

    const float* Wp[3] = {Wq, Wk, Wv};

    for (int k0 = 0; k0 < EMB; k0 += 32) {
        // X tile 64x32 = 512 float4 (2 per thread), coalesced
#pragma unroll
        for (int l = 0; l < 2; l++) {
            int idx = tid + l * 256;            // 0..511
            int r   = idx >> 3;                 // 8 float4 per row
            int c4  = idx & 7;
            float4 v = *(const float4*)(&x[(size_t)(row0 + r) * EMB + k0 + c4 * 4]);
            Xs[r][c4 * 4 + 0] = v.x;
            Xs[r][c4 * 4 + 1] = v.y;
            Xs[r][c4 * 4 + 2] = v.z;
            Xs[r][c4 * 4 + 3] = v.w;
        }
        // W tiles: 3 x (32x64) = 3 x 512 float4
#pragma unroll
        for (int m = 0; m < 3; m++) {
#pragma unroll
            for (int l = 0; l < 2; l++) {
                int idx = tid + l * 256;
                int r   = idx >> 4;             // 16 float4 per row
                int c4  = idx & 15;
                float4 v = *(const float4*)(&Wp[m][(size_t)(k0 + r) * HS + c4 * 4]);
                *(float4*)(&Ws[m][r][c4 * 4]) = v;
            }
        }
        __syncthreads();

#pragma unroll
        for (int kk = 0; kk < 32; kk++) {
            float xv[4];
#pragma unroll
            for (int i = 0; i < 4; i++) xv[i] = Xs[ty * 4 + i][kk];
#pragma unroll
            for (int m = 0; m < 3; m++) {
                float wv[4];
#pragma unroll
                for (int j = 0; j < 4; j++) wv[j] = Ws[m][kk][tx * 4 + j];
#pragma unroll
                for (int i = 0; i < 4; i++)
#pragma unroll
                    for (int j = 0; j < 4; j++)
                        acc[m][i][j] += xv[i] * wv[j];
            }
        }
        __syncthreads();
    }

#pragma unroll
    for (int i = 0; i < 4; i++) {
        size_t r = (size_t)(row0 + ty * 4 + i) * HS + tx * 4;
#pragma unroll
        for (int j = 0; j < 4; j++) g_q[r + j] = acc[0][i][j];
#pragma unroll
        for (int j = 0; j < 4; j++) g_k[r + j] = acc[1][i][j];
#pragma unroll
        for (int j = 0; j < 4; j++) g_v[r + j] = acc[2][i][j];
    }
}

// ---------------------------------------------------------------------------
// Flash-attention kernel (causal), fp32.
// grid = (T/64, B), 256 threads. BM = BN = 64, D = 64.
// Online softmax: running max m[i], running sum l[i] per query row.
// Smem: Qs[64][65], KP[64][65] (K tile, reused for P), Vs[64][65] -> 49920 B.
// ---------------------------------------------------------------------------
__global__ __launch_bounds__(256) void attn_kernel(float* __restrict__ out)
{
    extern __shared__ float sm[];
    float* Qs = sm;                 // 64*65
    float* KP = sm + 64 * 65;       // 64*65 (K, then P)
    float* Vs = sm + 2 * 64 * 65;   // 64*65

    const int tid = threadIdx.x;
    const int tx  = tid & 15;
    const int ty  = tid >> 4;
    const int b   = blockIdx.y;
    const int i0  = blockIdx.x * 64;                 // query tile start
    const size_t base = (size_t)b * TT * HS;

    // Load Q tile, folding in scale = EMB^-0.5 = 1/32 (exact power of two)
    const float sc = 0.03125f;
#pragma unroll
    for (int l = 0; l < 4; l++) {
        int idx = tid + l * 256;                     // 64 rows * 16 float4
        int r   = idx >> 4;
        int c4  = idx & 15;
        float4 v = *(const float4*)(&g_q[base + (size_t)(i0 + r) * HS + c4 * 4]);
        Qs[r * 65 + c4 * 4 + 0] = v.x * sc;
        Qs[r * 65 + c4 * 4 + 1] = v.y * sc;
        Qs[r * 65 + c4 * 4 + 2] = v.z * sc;
        Qs[r * 65 + c4 * 4 + 3] = v.w * sc;
    }

    float m[4], lsum[4], acc[4][4];
#pragma unroll
    for (int i = 0; i < 4; i++) { m[i] = -1e30f; lsum[i] = 0.0f; }
#pragma unroll
    for (int i = 0; i < 4; i++)
#pragma unroll
        for (int j = 0; j < 4; j++) acc[i][j] = 0.0f;

    for (int j0 = 0; j0 <= i0; j0 += 64) {
        __syncthreads();   // previous iteration's PV reads of KP/Vs complete

        // Load K, V tiles (coalesced float4 from global, scalar stores to padded smem)
#pragma unroll
        for (int l = 0; l < 4; l++) {
            int idx = tid + l * 256;
            int r   = idx >> 4;
            int c4  = idx & 15;
            float4 kv = *(const float4*)(&g_k[base + (size_t)(j0 + r) * HS + c4 * 4]);
            KP[r * 65 + c4 * 4 + 0] = kv.x;
            KP[r * 65 + c4 * 4 + 1] = kv.y;
            KP[r * 65 + c4 * 4 + 2] = kv.z;
            KP[r * 65 + c4 * 4 + 3] = kv.w;
            float4 vv = *(const float4*)(&g_v[base + (size_t)(j0 + r) * HS + c4 * 4]);
            Vs[r * 65 + c4 * 4 + 0] = vv.x;
            Vs[r * 65 + c4 * 4 + 1] = vv.y;
            Vs[r * 65 + c4 * 4 + 2] = vv.z;
            Vs[r * 65 + c4 * 4 + 3] = vv.w;
        }
        __syncthreads();

        // S = Q * K^T  (thread owns rows ty*4.., cols tx*4..)
        float s[4][4];
#pragma unroll
        for (int i = 0; i < 4; i++)
#pragma unroll
            for (int j = 0; j < 4; j++) s[i][j] = 0.0f;

#pragma unroll 8
        for (int kk = 0; kk < 64; kk++) {
            float qv[4], kv[4];
#pragma unroll
            for (int i = 0; i < 4; i++) qv[i] = Qs[(ty * 4 + i) * 65 + kk];
#pragma unroll
            for (int j = 0; j < 4; j++) kv[j] = KP[(tx * 4 + j) * 65 + kk];
#pragma unroll
            for (int i = 0; i < 4; i++)
#pragma unroll
                for (int j = 0; j < 4; j++) s[i][j] += qv[i] * kv[j];
        }

        // Causal mask (only the diagonal tile needs it)
        if (j0 == i0) {
#pragma unroll
            for (int i = 0; i < 4; i++) {
                int qidx = ty * 4 + i;
#pragma unroll
                for (int j = 0; j < 4; j++) {
                    if (tx * 4 + j > qidx) s[i][j] = -1e30f;
                }
            }
        }

        // Online softmax per row (row spans 16 consecutive lanes -> shfl width 16)
#pragma unroll
        for (int i = 0; i < 4; i++) {
            float mloc = fmaxf(fmaxf(s[i][0], s[i][1]), fmaxf(s[i][2], s[i][3]));
#pragma unroll
            for (int off = 8; off >= 1; off >>= 1)
                mloc = fmaxf(mloc, __shfl_xor_sync(0xffffffffu, mloc, off, 16));
            float mnew = fmaxf(m[i], mloc);
            float corr = __expf(m[i] - mnew);
            m[i] = mnew;

            float psum = 0.0f;
#pragma unroll
            for (int j = 0; j < 4; j++) {
                float p = __expf(s[i][j] - mnew);   // masked -1e30 underflows to 0
                s[i][j] = p;
                psum += p;
            }
#pragma unroll
            for (int off = 8; off >= 1; off >>= 1)
                psum += __shfl_xor_sync(0xffffffffu, psum, off, 16);

            lsum[i] = lsum[i] * corr + psum;
#pragma unroll
            for (int j = 0; j < 4; j++) acc[i][j] *= corr;
        }

        __syncthreads();   // all warps done reading K from KP

        // Write P into KP (same [row][65] layout)
#pragma unroll
        for (int i = 0; i < 4; i++)
#pragma unroll
            for (int j = 0; j < 4; j++)
                KP[(ty * 4 + i) * 65 + tx * 4 + j] = s[i][j];
        __syncthreads();

        // O += P @ V   (contraction over key index ss)
#pragma unroll 8
        for (int ss = 0; ss < 64; ss++) {
            float pv[4], vv[4];
#pragma unroll
            for (int i = 0; i < 4; i++) pv[i] = KP[(ty * 4 + i) * 65 + ss];
#pragma unroll
            for (int j = 0; j < 4; j++) vv[j] = Vs[ss * 65 + tx * 4 + j];
#pragma unroll
            for (int i = 0; i < 4; i++)
#pragma unroll
                for (int j = 0; j < 4; j++) acc[i][j] += pv[i] * vv[j];
        }
    }

    // Epilogue: out = acc / l
#pragma unroll
    for (int i = 0; i < 4; i++) {
        float inv = 1.0f / lsum[i];
        size_t r = base + (size_t)(i0 + ty * 4 + i) * HS + tx * 4;
#pragma unroll
        for (int j = 0; j < 4; j++) out[r + j] = acc[i][j] * inv;
    }
}

// ---------------------------------------------------------------------------
// kernel_launch: proj -> attention. Graph-capturable, allocation-free.
// Inputs (metadata order): x [B,T,E], Wq [E,H], Wk [E,H], Wv [E,H], all fp32.
// Output: [B,T,H] fp32.
// ---------------------------------------------------------------------------
extern "C" void kernel_launch(void* const* d_in, const int* in_sizes, int n_in,
                              void* d_out, int out_size)
{
    const float* x  = (const float*)d_in[0];
    const float* Wq = (const float*)d_in[1];
    const float* Wk = (const float*)d_in[2];
    const float* Wv = (const float*)d_in[3];
    float* out = (float*)d_out;

    proj_kernel<<<NROWS / 64, 256>>>(x, Wq, Wk, Wv);

    const int smem = 3 * 64 * 65 * (int)sizeof(float);   // 49920 B > 48K default
    cudaFuncSetAttribute(attn_kernel, cudaFuncAttributeMaxDynamicSharedMemorySize, smem);
    attn_kernel<<<dim3(TT / 64, BB), 256, smem>>>(out);
}

// round 17
// speedup vs baseline: 1.3939x; 1.3923x over previous
#include <cuda_runtime.h>
#include <math.h>

// Problem constants
#define EMB   1024
#define HS    64
#define BB    4
#define TT    4096
#define NROWS (BB * TT)   // 16384
#define SPL   4           // KV splits per query tile

// Scratch (device globals; no allocations allowed)
__device__ float g_q[NROWS * HS];
__device__ float g_k[NROWS * HS];
__device__ float g_v[NROWS * HS];
// Split-KV partials: indexed by part = ((s*BB + b)*64 + qtile)
__device__ float g_pm[SPL * BB * 64 * 64];             // row max
__device__ float g_pl[SPL * BB * 64 * 64];             // row sum
__device__ float g_po[(size_t)SPL * BB * 64 * 64 * 64]; // partial O (16 MB)

// ---------------------------------------------------------------------------
// Fused projection kernel: q = x@Wq, k = x@Wk, v = x@Wv  (at FFMA roofline)
// ---------------------------------------------------------------------------
__global__ __launch_bounds__(256) void proj_kernel(
    const float* __restrict__ x,
    const float* __restrict__ Wq,
    const float* __restrict__ Wk,
    const float* __restrict__ Wv)
{
    __shared__ float Xs[64][33];
    __shared__ float Ws[3][32][64];

    const int tid = threadIdx.x;
    const int tx  = tid & 15;
    const int ty  = tid >> 4;
    const int row0 = blockIdx.x * 64;

    float acc[3][4][4];
#pragma unroll
    for (int m = 0; m < 3; m++)
#pragma unroll
        for (int i = 0; i < 4; i++)
#pragma unroll
            for (int j = 0; j < 4; j++) acc[m][i][j] = 0.0f;

    const float* Wp[3] = {Wq, Wk, Wv};

    for (int k0 = 0; k0 < EMB; k0 += 32) {
#pragma unroll
        for (int l = 0; l < 2; l++) {
            int idx = tid + l * 256;
            int r   = idx >> 3;
            int c4  = idx & 7;
            float4 v = *(const float4*)(&x[(size_t)(row0 + r) * EMB + k0 + c4 * 4]);
            Xs[r][c4 * 4 + 0] = v.x;
            Xs[r][c4 * 4 + 1] = v.y;
            Xs[r][c4 * 4 + 2] = v.z;
            Xs[r][c4 * 4 + 3] = v.w;
        }
#pragma unroll
        for (int m = 0; m < 3; m++) {
#pragma unroll
            for (int l = 0; l < 2; l++) {
                int idx = tid + l * 256;
                int r   = idx >> 4;
                int c4  = idx & 15;
                float4 v = *(const float4*)(&Wp[m][(size_t)(k0 + r) * HS + c4 * 4]);
                *(float4*)(&Ws[m][r][c4 * 4]) = v;
            }
        }
        __syncthreads();

#pragma unroll
        for (int kk = 0; kk < 32; kk++) {
            float xv[4];
#pragma unroll
            for (int i = 0; i < 4; i++) xv[i] = Xs[ty * 4 + i][kk];
#pragma unroll
            for (int m = 0; m < 3; m++) {
                float wv[4];
#pragma unroll
                for (int j = 0; j < 4; j++) wv[j] = Ws[m][kk][tx * 4 + j];
#pragma unroll
                for (int i = 0; i < 4; i++)
#pragma unroll
                    for (int j = 0; j < 4; j++)
                        acc[m][i][j] += xv[i] * wv[j];
            }
        }
        __syncthreads();
    }

#pragma unroll
    for (int i = 0; i < 4; i++) {
        size_t r = (size_t)(row0 + ty * 4 + i) * HS + tx * 4;
#pragma unroll
        for (int j = 0; j < 4; j++) g_q[r + j] = acc[0][i][j];
#pragma unroll
        for (int j = 0; j < 4; j++) g_k[r + j] = acc[1][i][j];
#pragma unroll
        for (int j = 0; j < 4; j++) g_v[r + j] = acc[2][i][j];
    }
}

// ---------------------------------------------------------------------------
// Split-KV flash-attention kernel (causal), fp32, vectorized LDS.
// grid = (64 qtiles, SPL splits, BB batch), 256 threads.
// Q/K/V tiles: stride-64 rows, chunk-XOR swizzle -> conflict-free LDS.128.
// P stored transposed (stride 68) so PV reads are LDS.128 too.
// ---------------------------------------------------------------------------
__global__ __launch_bounds__(256, 3) void attn_kernel()
{
    extern __shared__ float sm[];
    float* Qs = sm;                     // 64*64 swizzled
    float* Ks = sm + 64 * 64;           // 64*64 swizzled
    float* Vs = sm + 2 * 64 * 64;       // 64*64 swizzled
    float* Pt = sm + 3 * 64 * 64;       // [key][qrow], stride 68

    const int tid = threadIdx.x;
    const int tx  = tid & 15;
    const int ty  = tid >> 4;
    const int q   = blockIdx.x;          // query tile 0..63
    const int s   = blockIdx.y;          // split 0..SPL-1
    const int b   = blockIdx.z;
    const int i0  = q * 64;
    const size_t base = (size_t)b * TT * HS;

    // KV tile range for this split
    const int n  = q + 1;
    const int lo = (n * s) / SPL;
    const int hi = (n * (s + 1)) / SPL;

    float m[4], lsum[4], acc[4][4];
#pragma unroll
    for (int i = 0; i < 4; i++) { m[i] = -1e30f; lsum[i] = 0.0f; }
#pragma unroll
    for (int i = 0; i < 4; i++)
#pragma unroll
        for (int j = 0; j < 4; j++) acc[i][j] = 0.0f;

    if (lo < hi) {
        // Load Q tile with swizzle; fold scale = EMB^-0.5 = 1/32
        const float sc = 0.03125f;
#pragma unroll
        for (int l = 0; l < 4; l++) {
            int idx = tid + l * 256;
            int r   = idx >> 4;
            int c4  = idx & 15;
            float4 v = *(const float4*)(&g_q[base + (size_t)(i0 + r) * HS + c4 * 4]);
            float4 vs = make_float4(v.x * sc, v.y * sc, v.z * sc, v.w * sc);
            *(float4*)(&Qs[r * 64 + ((c4 ^ (r >> 2)) & 15) * 4]) = vs;
        }

        for (int jt = lo; jt < hi; jt++) {
            const int j0 = jt * 64;
            __syncthreads();   // prior PV done reading Pt/Vs before overwrite

            // Load K, V tiles (coalesced gmem float4, swizzled smem float4 stores)
#pragma unroll
            for (int l = 0; l < 4; l++) {
                int idx = tid + l * 256;
                int r   = idx >> 4;
                int c4  = idx & 15;
                int sw  = r * 64 + ((c4 ^ (r >> 2)) & 15) * 4;
                float4 kv = *(const float4*)(&g_k[base + (size_t)(j0 + r) * HS + c4 * 4]);
                *(float4*)(&Ks[sw]) = kv;
                float4 vv = *(const float4*)(&g_v[base + (size_t)(j0 + r) * HS + c4 * 4]);
                *(float4*)(&Vs[sw]) = vv;
            }
            __syncthreads();

            // S = Q * K^T : dot4 over kk chunks, all operands LDS.128
            float sv[4][4];
#pragma unroll
            for (int i = 0; i < 4; i++)
#pragma unroll
                for (int j = 0; j < 4; j++) sv[i][j] = 0.0f;

#pragma unroll
            for (int c = 0; c < 16; c++) {
                float4 q4[4], k4[4];
#pragma unroll
                for (int i = 0; i < 4; i++)
                    q4[i] = *(const float4*)(&Qs[(ty * 4 + i) * 64 + ((c ^ ty) & 15) * 4]);
#pragma unroll
                for (int j = 0; j < 4; j++)
                    k4[j] = *(const float4*)(&Ks[(tx * 4 + j) * 64 + ((c ^ tx) & 15) * 4]);
#pragma unroll
                for (int i = 0; i < 4; i++)
#pragma unroll
                    for (int j = 0; j < 4; j++) {
                        sv[i][j] += q4[i].x * k4[j].x;
                        sv[i][j] += q4[i].y * k4[j].y;
                        sv[i][j] += q4[i].z * k4[j].z;
                        sv[i][j] += q4[i].w * k4[j].w;
                    }
            }

            // Causal mask on the diagonal tile
            if (jt == q) {
#pragma unroll
                for (int i = 0; i < 4; i++) {
                    int qidx = ty * 4 + i;
#pragma unroll
                    for (int j = 0; j < 4; j++)
                        if (tx * 4 + j > qidx) sv[i][j] = -1e30f;
                }
            }

            // Online softmax per row (row = 16 lanes, shfl width 16)
#pragma unroll
            for (int i = 0; i < 4; i++) {
                float mloc = fmaxf(fmaxf(sv[i][0], sv[i][1]), fmaxf(sv[i][2], sv[i][3]));
#pragma unroll
                for (int off = 8; off >= 1; off >>= 1)
                    mloc = fmaxf(mloc, __shfl_xor_sync(0xffffffffu, mloc, off, 16));
                float mnew = fmaxf(m[i], mloc);
                float corr = __expf(m[i] - mnew);
                m[i] = mnew;

                float psum = 0.0f;
#pragma unroll
                for (int j = 0; j < 4; j++) {
                    float p = __expf(sv[i][j] - mnew);
                    sv[i][j] = p;
                    psum += p;
                }
#pragma unroll
                for (int off = 8; off >= 1; off >>= 1)
                    psum += __shfl_xor_sync(0xffffffffu, psum, off, 16);

                lsum[i] = lsum[i] * corr + psum;
#pragma unroll
                for (int j = 0; j < 4; j++) acc[i][j] *= corr;
            }

            // Write P transposed: Pt[key][qrow]
#pragma unroll
            for (int i = 0; i < 4; i++)
#pragma unroll
                for (int j = 0; j < 4; j++)
                    Pt[(tx * 4 + j) * 68 + ty * 4 + i] = sv[i][j];
            __syncthreads();

            // O += P @ V : per key ss, pv/vv are LDS.128
#pragma unroll 8
            for (int ss = 0; ss < 64; ss++) {
                float4 p4 = *(const float4*)(&Pt[ss * 68 + ty * 4]);
                float4 v4 = *(const float4*)(&Vs[ss * 64 + ((tx ^ ((ss >> 2) & 15)) & 15) * 4]);
                float pv[4] = {p4.x, p4.y, p4.z, p4.w};
                float vv[4] = {v4.x, v4.y, v4.z, v4.w};
#pragma unroll
                for (int i = 0; i < 4; i++)
#pragma unroll
                    for (int j = 0; j < 4; j++)
                        acc[i][j] += pv[i] * vv[j];
            }
        }
    }

    // Write partials (no normalization here)
    const int part = (s * BB + b) * 64 + q;
#pragma unroll
    for (int i = 0; i < 4; i++) {
        if (tx == 0) {
            g_pm[part * 64 + ty * 4 + i] = m[i];
            g_pl[part * 64 + ty * 4 + i] = lsum[i];
        }
        float4 o = make_float4(acc[i][0], acc[i][1], acc[i][2], acc[i][3]);
        *(float4*)(&g_po[(size_t)part * 4096 + (size_t)(ty * 4 + i) * 64 + tx * 4]) = o;
    }
}

// ---------------------------------------------------------------------------
// Combine kernel: merge SPL partials per (b, qtile), normalize, write out.
// ---------------------------------------------------------------------------
__global__ __launch_bounds__(256) void combine_kernel(float* __restrict__ out)
{
    __shared__ float f[SPL][64];
    __shared__ float invl[64];

    const int q   = blockIdx.x;
    const int b   = blockIdx.y;
    const int tid = threadIdx.x;

    if (tid < 64) {
        float mm[SPL];
        float mx = -1e30f;
#pragma unroll
        for (int s = 0; s < SPL; s++) {
            mm[s] = g_pm[((s * BB + b) * 64 + q) * 64 + tid];
            mx = fmaxf(mx, mm[s]);
        }
        float l = 0.0f;
#pragma unroll
        for (int s = 0; s < SPL; s++) {
            float e = __expf(mm[s] - mx);
            f[s][tid] = e;
            l += g_pl[((s * BB + b) * 64 + q) * 64 + tid] * e;
        }
        invl[tid] = 1.0f / l;
    }
    __syncthreads();

    const int r  = tid >> 2;           // 0..63
    const int c0 = (tid & 3) * 16;
#pragma unroll
    for (int u = 0; u < 4; u++) {
        int c = c0 + u * 4;
        float4 o = make_float4(0.f, 0.f, 0.f, 0.f);
#pragma unroll
        for (int s = 0; s < SPL; s++) {
            float4 p = *(const float4*)(&g_po[(size_t)((s * BB + b) * 64 + q) * 4096
                                              + (size_t)r * 64 + c]);
            float e = f[s][r];
            o.x += p.x * e; o.y += p.y * e; o.z += p.z * e; o.w += p.w * e;
        }
        float iv = invl[r];
        o.x *= iv; o.y *= iv; o.z *= iv; o.w *= iv;
        *(float4*)(&out[(size_t)b * TT * HS + (size_t)(q * 64 + r) * HS + c]) = o;
    }
}

// ---------------------------------------------------------------------------
// kernel_launch: proj -> split-KV attention -> combine. Graph-capturable.
// ---------------------------------------------------------------------------
extern "C" void kernel_launch(void* const* d_in, const int* in_sizes, int n_in,
                              void* d_out, int out_size)
{
    const float* x  = (const float*)d_in[0];
    const float* Wq = (const float*)d_in[1];
    const float* Wk = (const float*)d_in[2];
    const float* Wv = (const float*)d_in[3];
    float* out = (float*)d_out;

    proj_kernel<<<NROWS / 64, 256>>>(x, Wq, Wk, Wv);

    const int smem = (3 * 64 * 64 + 64 * 68) * (int)sizeof(float);   // 66560 B
    cudaFuncSetAttribute(attn_kernel, cudaFuncAttributeMaxDynamicSharedMemorySize, smem);
    attn_kernel<<<dim3(64, SPL, BB), 256, smem>>>();

    combine_kernel<<<dim3(64, BB), 256>>>(out);
}